// round 5
// baseline (speedup 1.0000x reference)
#include <cuda_runtime.h>

// DCN cross, B=8192, D=256, L=4.
//   out = a_L * x0 + v_L,  a_{l+1} = a_l*(1+d_l) + c_l,
//   d_l = x0.W_l (per row), c_l = v_l.W_l and v_l row-independent.
// Mapping: 8 lanes per row (3-step xor ladder), 4 rows/warp, 4 warps/block.
// v/c computed once per block into smem (preamble), not per warp.

constexpr int D = 256;
constexpr int L = 4;
constexpr int ROWS_PER_BLOCK = 16;   // 4 warps * 4 rows

__global__ __launch_bounds__(128, 6)
void cross_kernel(const float* __restrict__ x,
                  const float* __restrict__ W,
                  const float* __restrict__ b_lin,
                  const float* __restrict__ bias,
                  float* __restrict__ out,
                  int B)
{
    __shared__ float v_sm[D];        // v_L vector (row-independent)
    __shared__ float c_sm[4 * L];    // per-warp partial c_l

    const int tid  = threadIdx.x;
    const int warp = tid >> 5;
    const int lane = tid & 31;
    const int j    = lane & 7;       // lane within 8-lane row group

    // ---------- preamble: v_L and c_l (row-independent), once per block ----------
    {
        float cp[L];
        float v0 = 0.0f, v1 = 0.0f;
        const int d0 = tid, d1 = tid + 128;
        #pragma unroll
        for (int l = 0; l < L; ++l) {
            cp[l] = v0 * W[l * D + d0] + v1 * W[l * D + d1];  // c_l uses v BEFORE update
            const float bl = b_lin[l];
            v0 += bl + bias[l * D + d0];
            v1 += bl + bias[l * D + d1];
        }
        v_sm[d0] = v0;
        v_sm[d1] = v1;
        #pragma unroll
        for (int o = 16; o > 0; o >>= 1) {
            #pragma unroll
            for (int l = 0; l < L; ++l)
                cp[l] += __shfl_xor_sync(0xffffffffu, cp[l], o);
        }
        if (lane == 0) {
            #pragma unroll
            for (int l = 0; l < L; ++l) c_sm[warp * L + l] = cp[l];
        }
    }
    __syncthreads();

    float c[L];
    #pragma unroll
    for (int l = 0; l < L; ++l)
        c[l] = (c_sm[0 * L + l] + c_sm[1 * L + l]) + (c_sm[2 * L + l] + c_sm[3 * L + l]);

    // ---------- main: 1 row per 8-lane group ----------
    const int row = blockIdx.x * ROWS_PER_BLOCK + warp * 4 + (lane >> 3);
    if (row >= B) return;

    // k-major interleaved ownership: lane j owns float4s {k*8+j}, so each
    // LDG.128 covers one full 128B line per row group (fully coalesced).
    const float4* xr = reinterpret_cast<const float4*>(x + (size_t)row * D);
    float4 xq[8];
    #pragma unroll
    for (int k = 0; k < 8; ++k) xq[k] = xr[k * 8 + j];

    // d_l = x0 . W_l : 4 independent dots (ILP across layers + float4 components)
    float d[L];
    #pragma unroll
    for (int l = 0; l < L; ++l) {
        const float4* Wr = reinterpret_cast<const float4*>(W + l * D);
        float a0 = 0.f, a1 = 0.f, a2 = 0.f, a3 = 0.f;
        #pragma unroll
        for (int k = 0; k < 8; ++k) {
            const float4 w = Wr[k * 8 + j];
            a0 = fmaf(xq[k].x, w.x, a0);
            a1 = fmaf(xq[k].y, w.y, a1);
            a2 = fmaf(xq[k].z, w.z, a2);
            a3 = fmaf(xq[k].w, w.w, a3);
        }
        d[l] = (a0 + a1) + (a2 + a3);
    }

    // 3-step width-8 ladder; one ladder reduces all 4 rows of the warp at once
    #pragma unroll
    for (int o = 4; o > 0; o >>= 1) {
        #pragma unroll
        for (int l = 0; l < L; ++l)
            d[l] += __shfl_xor_sync(0xffffffffu, d[l], o);
    }

    // scalar recurrence: a_{l+1} = a_l*(1+d_l) + c_l
    float a = 1.0f;
    #pragma unroll
    for (int l = 0; l < L; ++l)
        a = fmaf(a, d[l], a + c[l]);

    // out = a * x0 + v_L
    const float4* vr = reinterpret_cast<const float4*>(v_sm);
    float4* orow = reinterpret_cast<float4*>(out + (size_t)row * D);
    #pragma unroll
    for (int k = 0; k < 8; ++k) {
        const float4 v = vr[k * 8 + j];
        float4 o4;
        o4.x = fmaf(a, xq[k].x, v.x);
        o4.y = fmaf(a, xq[k].y, v.y);
        o4.z = fmaf(a, xq[k].z, v.z);
        o4.w = fmaf(a, xq[k].w, v.w);
        orow[k * 8 + j] = o4;
    }
}

extern "C" void kernel_launch(void* const* d_in, const int* in_sizes, int n_in,
                              void* d_out, int out_size)
{
    const float* x     = (const float*)d_in[0];
    const float* W     = (const float*)d_in[1];
    const float* b_lin = (const float*)d_in[2];
    const float* bias  = (const float*)d_in[3];
    float* out         = (float*)d_out;

    const int B = in_sizes[0] / D;   // 8192
    const int blocks = (B + ROWS_PER_BLOCK - 1) / ROWS_PER_BLOCK;  // 512

    cross_kernel<<<blocks, 128>>>(x, W, b_lin, bias, out, B);
}

// round 6
// speedup vs baseline: 1.0294x; 1.0294x over previous
#include <cuda_runtime.h>

// DCN cross, B=8192, D=256, L=4, algebraic collapse:
//   out = a_L * x0 + v_L,  a_{l+1} = a_l*(1+d_l) + c_l
//   d_l = x0.W_l (per-row), c_l/v_l row-independent (block preamble -> smem).
// Mapping: 8 lanes/row, 4 rows/warp, 8 warps/block (32 rows/block),
// grid = 256 blocks -> single resident wave on 148 SMs.

constexpr int D = 256;
constexpr int L = 4;
constexpr int ROWS_PER_BLOCK = 32;

__global__ __launch_bounds__(256)
void cross_kernel(const float* __restrict__ x,
                  const float* __restrict__ W,
                  const float* __restrict__ b_lin,
                  const float* __restrict__ bias,
                  float* __restrict__ out,
                  int B)
{
    __shared__ float W_sm[L * D];     // 4 KB
    __shared__ float v_sm[D];         // 1 KB
    __shared__ float c_part[8 * L];   // per-warp c partials
    __shared__ float c_sm[L];

    const int tid  = threadIdx.x;
    const int warp = tid >> 5;
    const int lane = tid & 31;
    const int j    = lane & 7;                       // lane within row group
    const int row  = blockIdx.x * ROWS_PER_BLOCK + warp * 4 + (lane >> 3);

    // ---- issue x loads FIRST (latency hidden behind preamble) ----
    // lane j owns float4 slots {k*8+j}: every LDG.128 quartet covers full lines.
    const float4* xr = reinterpret_cast<const float4*>(x + (size_t)row * D);
    float4 xq[8];
    #pragma unroll
    for (int k = 0; k < 8; ++k) xq[k] = xr[k * 8 + j];

    // ---- preamble: W -> smem, v_L vector, c_l scalars (once per block) ----
    {
        float v = 0.0f;
        float cp[L];
        #pragma unroll
        for (int l = 0; l < L; ++l) {
            const float w = W[l * D + tid];
            W_sm[l * D + tid] = w;
            cp[l] = v * w;                       // c_l uses v BEFORE update
            v += b_lin[l] + bias[l * D + tid];
        }
        v_sm[tid] = v;
        #pragma unroll
        for (int o = 16; o > 0; o >>= 1) {
            #pragma unroll
            for (int l = 0; l < L; ++l)
                cp[l] += __shfl_xor_sync(0xffffffffu, cp[l], o);
        }
        if (lane == 0) {
            #pragma unroll
            for (int l = 0; l < L; ++l) c_part[warp * L + l] = cp[l];
        }
    }
    __syncthreads();
    if (tid < L) {
        float s = 0.0f;
        #pragma unroll
        for (int w8 = 0; w8 < 8; ++w8) s += c_part[w8 * L + tid];
        c_sm[tid] = s;
    }
    __syncthreads();

    // ---- dots: d_l = x0 . W_l (W from smem, broadcast across row groups) ----
    const float4* Wv = reinterpret_cast<const float4*>(W_sm);
    float d[L];
    #pragma unroll
    for (int l = 0; l < L; ++l) {
        float a0 = 0.f, a1 = 0.f, a2 = 0.f, a3 = 0.f;
        #pragma unroll
        for (int k = 0; k < 8; ++k) {
            const float4 w = Wv[l * 64 + k * 8 + j];
            a0 = fmaf(xq[k].x, w.x, a0);
            a1 = fmaf(xq[k].y, w.y, a1);
            a2 = fmaf(xq[k].z, w.z, a2);
            a3 = fmaf(xq[k].w, w.w, a3);
        }
        d[l] = (a0 + a1) + (a2 + a3);
    }

    // ---- 3-step width-8 ladder: reduces all 4 rows of the warp per SHFL ----
    #pragma unroll
    for (int o = 4; o > 0; o >>= 1) {
        #pragma unroll
        for (int l = 0; l < L; ++l)
            d[l] += __shfl_xor_sync(0xffffffffu, d[l], o);
    }

    // ---- scalar recurrence + streaming epilogue ----
    float a = 1.0f;
    #pragma unroll
    for (int l = 0; l < L; ++l)
        a = fmaf(a, d[l], a + c_sm[l]);          // a += a*d_l + c_l

    const float4* vr = reinterpret_cast<const float4*>(v_sm);
    float4* orow = reinterpret_cast<float4*>(out + (size_t)row * D);
    #pragma unroll
    for (int k = 0; k < 8; ++k) {
        const float4 v = vr[k * 8 + j];
        float4 o4;
        o4.x = fmaf(a, xq[k].x, v.x);
        o4.y = fmaf(a, xq[k].y, v.y);
        o4.z = fmaf(a, xq[k].z, v.z);
        o4.w = fmaf(a, xq[k].w, v.w);
        orow[k * 8 + j] = o4;
    }
}

extern "C" void kernel_launch(void* const* d_in, const int* in_sizes, int n_in,
                              void* d_out, int out_size)
{
    const float* x     = (const float*)d_in[0];
    const float* W     = (const float*)d_in[1];
    const float* b_lin = (const float*)d_in[2];
    const float* bias  = (const float*)d_in[3];
    float* out         = (float*)d_out;

    const int B = in_sizes[0] / D;                              // 8192
    const int blocks = (B + ROWS_PER_BLOCK - 1) / ROWS_PER_BLOCK; // 256

    cross_kernel<<<blocks, 256>>>(x, W, b_lin, bias, out, B);
}

// round 7
// speedup vs baseline: 1.0332x; 1.0037x over previous
#include <cuda_runtime.h>

// DCN cross, B=8192, D=256, L=4, collapsed algebra:
//   out = a_L * x0 + v_L,  a_{l+1} = a_l*(1+d_l) + c_l
//   d_l = x0.W_l (per-row), v_L / c_l row-independent (block preamble, smem).
// Mapping: 16 lanes/row, 2 rows/warp, 8 warps/block (16 rows/block),
// grid = 512 -> ~27 warps/SM; 4-step ladder reduces both rows per SHFL.

constexpr int D = 256;
constexpr int L = 4;
constexpr int ROWS_PER_BLOCK = 16;

__global__ __launch_bounds__(256)
void cross_kernel(const float* __restrict__ x,
                  const float* __restrict__ W,
                  const float* __restrict__ b_lin,
                  const float* __restrict__ bias,
                  float* __restrict__ out,
                  int B)
{
    __shared__ float W_sm[L * D];     // 4 KB
    __shared__ float v_sm[D];         // 1 KB
    __shared__ float c_part[8 * L];
    __shared__ float c_sm[L];

    const int tid  = threadIdx.x;
    const int warp = tid >> 5;
    const int lane = tid & 31;
    const int j    = lane & 15;                       // slot within 16-lane row group
    const int row  = blockIdx.x * ROWS_PER_BLOCK + warp * 2 + (lane >> 4);

    // ---- x loads issue first: 4 independent LDG.128, latency hides behind preamble
    // lane j owns float4 slots {k*16+j}: each LDG.128 covers whole 128B lines.
    const float4* xr = reinterpret_cast<const float4*>(x + (size_t)row * D);
    float4 xq[4];
    #pragma unroll
    for (int k = 0; k < 4; ++k) xq[k] = xr[k * 16 + j];

    // ---- preamble (once per block): W -> smem, v_L vector, c_l scalars ----
    {
        float v = 0.0f;
        float cp[L];
        #pragma unroll
        for (int l = 0; l < L; ++l) {
            const float w = W[l * D + tid];
            W_sm[l * D + tid] = w;
            cp[l] = v * w;                        // c_l uses v BEFORE update
            v += b_lin[l] + bias[l * D + tid];
        }
        v_sm[tid] = v;
        #pragma unroll
        for (int o = 16; o > 0; o >>= 1) {
            #pragma unroll
            for (int l = 0; l < L; ++l)
                cp[l] += __shfl_xor_sync(0xffffffffu, cp[l], o);
        }
        if (lane == 0) {
            #pragma unroll
            for (int l = 0; l < L; ++l) c_part[warp * L + l] = cp[l];
        }
    }
    __syncthreads();
    if (tid < L) {
        float s = 0.0f;
        #pragma unroll
        for (int w8 = 0; w8 < 8; ++w8) s += c_part[w8 * L + tid];
        c_sm[tid] = s;
    }
    __syncthreads();

    // ---- dots: d_l = x0 . W_l (W broadcast from smem) ----
    const float4* Wv = reinterpret_cast<const float4*>(W_sm);
    float d[L];
    #pragma unroll
    for (int l = 0; l < L; ++l) {
        float a0 = 0.f, a1 = 0.f, a2 = 0.f, a3 = 0.f;
        #pragma unroll
        for (int k = 0; k < 4; ++k) {
            const float4 w = Wv[l * 64 + k * 16 + j];
            a0 = fmaf(xq[k].x, w.x, a0);
            a1 = fmaf(xq[k].y, w.y, a1);
            a2 = fmaf(xq[k].z, w.z, a2);
            a3 = fmaf(xq[k].w, w.w, a3);
        }
        d[l] = (a0 + a1) + (a2 + a3);
    }

    // ---- 4-step width-16 ladder: one SHFL reduces both rows of the warp ----
    #pragma unroll
    for (int o = 8; o > 0; o >>= 1) {
        #pragma unroll
        for (int l = 0; l < L; ++l)
            d[l] += __shfl_xor_sync(0xffffffffu, d[l], o);
    }

    // ---- scalar recurrence + streaming epilogue ----
    float a = 1.0f;
    #pragma unroll
    for (int l = 0; l < L; ++l)
        a = fmaf(a, d[l], a + c_sm[l]);           // a += a*d_l + c_l

    const float4* vr = reinterpret_cast<const float4*>(v_sm);
    float4* orow = reinterpret_cast<float4*>(out + (size_t)row * D);
    #pragma unroll
    for (int k = 0; k < 4; ++k) {
        const float4 v = vr[k * 16 + j];
        float4 o4;
        o4.x = fmaf(a, xq[k].x, v.x);
        o4.y = fmaf(a, xq[k].y, v.y);
        o4.z = fmaf(a, xq[k].z, v.z);
        o4.w = fmaf(a, xq[k].w, v.w);
        orow[k * 16 + j] = o4;
    }
}

extern "C" void kernel_launch(void* const* d_in, const int* in_sizes, int n_in,
                              void* d_out, int out_size)
{
    const float* x     = (const float*)d_in[0];
    const float* W     = (const float*)d_in[1];
    const float* b_lin = (const float*)d_in[2];
    const float* bias  = (const float*)d_in[3];
    float* out         = (float*)d_out;

    const int B = in_sizes[0] / D;                                // 8192
    const int blocks = (B + ROWS_PER_BLOCK - 1) / ROWS_PER_BLOCK; // 512

    cross_kernel<<<blocks, 256>>>(x, W, b_lin, bias, out, B);
}